// round 14
// baseline (speedup 1.0000x reference)
#include <cuda_runtime.h>
#include <cuda_bf16.h>

#define N_NODES 50000
#define N_EDGES 800000
#define NFEAT 128
#define NHID 128
#define NOUT 64

#define NB_GEMM_C ((N_NODES + 127) / 128)     // 391
#define NBLK_SCAN ((N_NODES + 511) / 512)     // 98
#define NCTA 296                              // 2 CTAs/SM x 148 SMs, all co-resident
#define NTHREAD 256
#define NWARPS_TOT (NCTA * 8)

// ---------------- scratch (static __device__, no allocations) ----------------
__device__ __align__(16) __nv_bfloat16 g_support[N_NODES * 128];
__device__ __align__(16) float g_h[N_NODES * 128];
__device__ int   g_rowptr[N_NODES + 1];       // chunk-LOCAL exclusive prefix
__device__ int   g_cursor[N_NODES];
__device__ int   g_blocksum[128];             // exclusive chunk offsets
__device__ int   g_bar[2];                    // [0]=count, [1]=phase
__device__ __align__(16) int g_csr_ew[N_EDGES * 2];   // interleaved {src, w_bits}

// ---------------- helpers ----------------
__device__ __forceinline__ void ffma2(unsigned long long& d,
                                      unsigned long long a,
                                      unsigned long long b) {
    asm("fma.rn.f32x2 %0, %1, %2, %0;" : "+l"(d) : "l"(a), "l"(b));
}
__device__ __forceinline__ unsigned long long dup2(float x) {
    unsigned long long r;
    asm("mov.b64 %0, {%1, %1};" : "=l"(r) : "f"(x));
    return r;
}
__device__ __forceinline__ unsigned cvt_bf2(unsigned long long pair) {
    float lo, hi; unsigned r;
    asm("mov.b64 {%0, %1}, %2;" : "=f"(lo), "=f"(hi) : "l"(pair));
    asm("cvt.rn.bf16x2.f32 %0, %1, %2;" : "=r"(r) : "f"(hi), "f"(lo));
    return r;
}
__device__ __forceinline__ void bf2_ffma2(unsigned long long& acc,
                                          unsigned bits,
                                          unsigned long long w2) {
    unsigned lo = bits << 16;
    unsigned hi = bits & 0xffff0000u;
    unsigned long long v;
    asm("mov.b64 %0, {%1, %2};" : "=l"(v) : "r"(lo), "r"(hi));
    ffma2(acc, v, w2);
}
__device__ __forceinline__ float2 unpack2(unsigned long long pair) {
    float lo, hi;
    asm("mov.b64 {%0, %1}, %2;" : "=f"(lo), "=f"(hi) : "l"(pair));
    return make_float2(lo, hi);
}

// ---------------- device-wide barrier (sense reversal; all CTAs resident) ----
__device__ __forceinline__ void grid_sync(int& sense) {
    __syncthreads();
    if (threadIdx.x == 0) {
        __threadfence();
        int a = atomicAdd(&g_bar[0], 1);
        if (a == NCTA - 1) {
            g_bar[0] = 0;
            __threadfence();
            atomicExch(&g_bar[1], sense ^ 1);
        } else {
            while (atomicAdd(&g_bar[1], 0) == sense) { }
            __threadfence();
        }
    }
    __syncthreads();
    sense ^= 1;
}

// ---------------- GEMM body (smem passed in; As2/Bs alias one 48KB block) ----
template <int BN>
__device__ __noinline__ void gemm_body(const float* __restrict__ A,
                                       const float* __restrict__ B,
                                       __nv_bfloat16* __restrict__ C,
                                       int M, int block,
                                       unsigned char* smem_raw) {
    constexpr int K = 128, BM = 128, BK = 16;
    constexpr int TM = 8, TN = BN / 16, TN2 = TN / 2;
    constexpr int NSLAB = K / BK;                 // 8
    constexpr int A_IT = (BM * BK / 4) / 256;     // 2
    constexpr int B_IT = (BK * BN / 4) / 256;     // 2 / 1

    auto As2 = reinterpret_cast<unsigned long long (*)[BM]>(smem_raw);   // [2*BK][BM] 32KB
    auto Bs  = reinterpret_cast<float (*)[BN]>(smem_raw + 32768);        // [2*BK][BN]

    const int tid = threadIdx.x;
    const int m0  = block * BM;
    const int tx  = tid % 16;
    const int ty  = tid / 16;
    const int mm  = ty * TM;
    const int nn  = tx * TN;

    unsigned long long acc2[TM][TN2];
#pragma unroll
    for (int i = 0; i < TM; i++)
#pragma unroll
        for (int j = 0; j < TN2; j++) acc2[i][j] = 0ull;

    const float4* A4 = reinterpret_cast<const float4*>(A);
    const float4* B4 = reinterpret_cast<const float4*>(B);

    float4 areg[A_IT], breg[B_IT];

    auto load_global = [&](int s) {
#pragma unroll
        for (int it = 0; it < A_IT; it++) {
            int f  = tid + it * 256;
            int m  = f & (BM - 1);
            int kq = f >> 7;
            int gm = m0 + m;
            areg[it] = (gm < M) ? A4[gm * (K / 4) + (s * BK) / 4 + kq]
                                : make_float4(0.f, 0.f, 0.f, 0.f);
        }
#pragma unroll
        for (int it = 0; it < B_IT; it++) {
            int f = tid + it * 256;
            breg[it] = B4[(s * BK) * (BN / 4) + f];
        }
    };
    auto store_smem = [&](int buf) {
#pragma unroll
        for (int it = 0; it < A_IT; it++) {
            int f  = tid + it * 256;
            int m  = f & (BM - 1);
            int k  = (f >> 7) * 4;
            As2[buf * BK + k + 0][m] = dup2(areg[it].x);
            As2[buf * BK + k + 1][m] = dup2(areg[it].y);
            As2[buf * BK + k + 2][m] = dup2(areg[it].z);
            As2[buf * BK + k + 3][m] = dup2(areg[it].w);
        }
#pragma unroll
        for (int it = 0; it < B_IT; it++) {
            int f = tid + it * 256;
            reinterpret_cast<float4*>(&Bs[buf * BK][0])[f] = breg[it];
        }
    };
    auto compute = [&](int buf) {
#pragma unroll
        for (int k = 0; k < BK; k++) {
            unsigned long long a2[TM];
#pragma unroll
            for (int i2 = 0; i2 < TM / 2; i2++) {
                ulonglong2 av = *reinterpret_cast<const ulonglong2*>(&As2[buf * BK + k][mm + i2 * 2]);
                a2[i2 * 2 + 0] = av.x;
                a2[i2 * 2 + 1] = av.y;
            }
            unsigned long long b2[TN2];
#pragma unroll
            for (int j4 = 0; j4 < TN2 / 2; j4++) {
                ulonglong2 bv = *reinterpret_cast<const ulonglong2*>(&Bs[buf * BK + k][nn + j4 * 4]);
                b2[j4 * 2 + 0] = bv.x;
                b2[j4 * 2 + 1] = bv.y;
            }
#pragma unroll
            for (int i = 0; i < TM; i++)
#pragma unroll
                for (int j = 0; j < TN2; j++) ffma2(acc2[i][j], a2[i], b2[j]);
        }
    };

    load_global(0);
    store_smem(0);
    __syncthreads();

    for (int s = 0; s < NSLAB; s++) {
        int cur = s & 1;
        bool has_next = (s + 1) < NSLAB;
        if (has_next) load_global(s + 1);
        compute(cur);
        if (has_next) store_smem(cur ^ 1);
        __syncthreads();
    }

#pragma unroll
    for (int i = 0; i < TM; i++) {
        int row = m0 + mm + i;
        if (row < M) {
            unsigned r32[TN2];
#pragma unroll
            for (int j = 0; j < TN2; j++) r32[j] = cvt_bf2(acc2[i][j]);
            unsigned* outp = reinterpret_cast<unsigned*>(C + row * BN + nn);
            if constexpr (TN2 == 4) {
                *reinterpret_cast<uint4*>(outp) = make_uint4(r32[0], r32[1], r32[2], r32[3]);
            } else {
                *reinterpret_cast<uint2*>(outp) = make_uint2(r32[0], r32[1]);
            }
        }
    }
}

// ---------------- SpMM phase (persistent: warps stride over nodes) ----------
template <int D, bool RELU>
__device__ __noinline__ void spmm_phase(const __nv_bfloat16* __restrict__ sup,
                                        const float* __restrict__ bias,
                                        float* __restrict__ out) {
    const int lane = threadIdx.x & 31;
    const int gw0  = blockIdx.x * 8 + (threadIdx.x >> 5);
    const int4* ew4 = reinterpret_cast<const int4*>(g_csr_ew);
    const int2* ew2 = reinterpret_cast<const int2*>(g_csr_ew);

    for (int gw = gw0; gw < N_NODES; gw += NWARPS_TOT) {
        int s = g_rowptr[gw]     + g_blocksum[gw >> 9];
        int e = g_rowptr[gw + 1] + g_blocksum[(gw + 1) >> 9];

        if constexpr (D == 128) {
            const uint2* supv = reinterpret_cast<const uint2*>(sup);
            unsigned long long accA = 0ull, accB = 0ull;
            int i = s;

            auto edge = [&](int sn, float wn) {
                uint2 v = supv[sn * 32 + lane];
                unsigned long long w2 = dup2(wn);
                bf2_ffma2(accA, v.x, w2);
                bf2_ffma2(accB, v.y, w2);
            };

            if (i < e && (i & 1)) { int2 p = ew2[i]; edge(p.x, __int_as_float(p.y)); i++; }
            for (; i + 3 < e; i += 4) {
                int4 pa = ew4[i >> 1];
                int4 pb = ew4[(i >> 1) + 1];
                uint2 v0 = supv[pa.x * 32 + lane];
                uint2 v1 = supv[pa.z * 32 + lane];
                uint2 v2 = supv[pb.x * 32 + lane];
                uint2 v3 = supv[pb.z * 32 + lane];
                unsigned long long w0 = dup2(__int_as_float(pa.y));
                unsigned long long w1 = dup2(__int_as_float(pa.w));
                unsigned long long w2 = dup2(__int_as_float(pb.y));
                unsigned long long w3 = dup2(__int_as_float(pb.w));
                bf2_ffma2(accA, v0.x, w0); bf2_ffma2(accB, v0.y, w0);
                bf2_ffma2(accA, v1.x, w1); bf2_ffma2(accB, v1.y, w1);
                bf2_ffma2(accA, v2.x, w2); bf2_ffma2(accB, v2.y, w2);
                bf2_ffma2(accA, v3.x, w3); bf2_ffma2(accB, v3.y, w3);
            }
            for (; i + 1 < e; i += 2) {
                int4 pa = ew4[i >> 1];
                edge(pa.x, __int_as_float(pa.y));
                edge(pa.z, __int_as_float(pa.w));
            }
            if (i < e) { int2 p = ew2[i]; edge(p.x, __int_as_float(p.y)); }

            float2 a0 = unpack2(accA);
            float2 a1 = unpack2(accB);
            float4 b = reinterpret_cast<const float4*>(bias)[lane];
            float4 r;
            r.x = a0.x + b.x; r.y = a0.y + b.y;
            r.z = a1.x + b.z; r.w = a1.y + b.w;
            if (RELU) {
                r.x = fmaxf(r.x, 0.f); r.y = fmaxf(r.y, 0.f);
                r.z = fmaxf(r.z, 0.f); r.w = fmaxf(r.w, 0.f);
            }
            reinterpret_cast<float4*>(out)[gw * 32 + lane] = r;
        } else {  // D == 64
            const unsigned* supv = reinterpret_cast<const unsigned*>(sup);
            unsigned long long accA = 0ull;
            int i = s;

            auto edge = [&](int sn, float wn) {
                bf2_ffma2(accA, supv[sn * 32 + lane], dup2(wn));
            };

            if (i < e && (i & 1)) { int2 p = ew2[i]; edge(p.x, __int_as_float(p.y)); i++; }
            for (; i + 3 < e; i += 4) {
                int4 pa = ew4[i >> 1];
                int4 pb = ew4[(i >> 1) + 1];
                unsigned v0 = supv[pa.x * 32 + lane];
                unsigned v1 = supv[pa.z * 32 + lane];
                unsigned v2 = supv[pb.x * 32 + lane];
                unsigned v3 = supv[pb.z * 32 + lane];
                bf2_ffma2(accA, v0, dup2(__int_as_float(pa.y)));
                bf2_ffma2(accA, v1, dup2(__int_as_float(pa.w)));
                bf2_ffma2(accA, v2, dup2(__int_as_float(pb.y)));
                bf2_ffma2(accA, v3, dup2(__int_as_float(pb.w)));
            }
            for (; i + 1 < e; i += 2) {
                int4 pa = ew4[i >> 1];
                edge(pa.x, __int_as_float(pa.y));
                edge(pa.z, __int_as_float(pa.w));
            }
            if (i < e) { int2 p = ew2[i]; edge(p.x, __int_as_float(p.y)); }

            float2 a0 = unpack2(accA);
            float2 b = reinterpret_cast<const float2*>(bias)[lane];
            float2 r = make_float2(a0.x + b.x, a0.y + b.y);
            if (RELU) { r.x = fmaxf(r.x, 0.f); r.y = fmaxf(r.y, 0.f); }
            reinterpret_cast<float2*>(out)[gw * 32 + lane] = r;
        }
    }
}

// ---------------- the persistent kernel ----------------
__global__ void __launch_bounds__(NTHREAD, 2)
persistent_kernel(const float* __restrict__ x,
                  const int* __restrict__ edge_src,
                  const int* __restrict__ edge_dst,
                  const float* __restrict__ edge_w,
                  const float* __restrict__ W0, const float* __restrict__ b0,
                  const float* __restrict__ W1, const float* __restrict__ b1,
                  const float* __restrict__ W2, const float* __restrict__ b2,
                  const float* __restrict__ W3, const float* __restrict__ b3,
                  float* __restrict__ out) {
    __shared__ __align__(16) unsigned char smem_raw[49152];
    const int tid = threadIdx.x;
    const int cta = blockIdx.x;
    int sense = 0;

    // ph0: gemm0 tiles (x @ W0 -> support) + edge histogram
    for (int t = cta; t < NB_GEMM_C; t += NCTA)
        gemm_body<128>(x, W0, g_support, N_NODES, t, smem_raw);
    for (int e = cta * NTHREAD + tid; e < N_EDGES; e += NCTA * NTHREAD)
        atomicAdd(&g_cursor[edge_dst[e]], 1);
    grid_sync(sense);

    // ph1: chunk-local scans (512 nodes per chunk, 2 per thread) + cursor re-zero
    {
        int* sd = (int*)smem_raw;
        for (int c = cta; c < NBLK_SCAN; c += NCTA) {
            int i0 = c * 512 + 2 * tid, i1 = i0 + 1;
            int v0 = (i0 < N_NODES) ? g_cursor[i0] : 0;
            int v1 = (i1 < N_NODES) ? g_cursor[i1] : 0;
            if (i0 < N_NODES) g_cursor[i0] = 0;
            if (i1 < N_NODES) g_cursor[i1] = 0;
            int sval = v0 + v1;
            sd[tid] = sval;
            __syncthreads();
#pragma unroll
            for (int off = 1; off < 256; off <<= 1) {
                int t = (tid >= off) ? sd[tid - off] : 0;
                __syncthreads();
                sd[tid] += t;
                __syncthreads();
            }
            int excl = sd[tid] - sval;
            if (i0 <= N_NODES) g_rowptr[i0] = excl;
            if (i1 <= N_NODES) g_rowptr[i1] = excl + v0;
            if (tid == 255) g_blocksum[c] = sd[255];
        }
    }
    grid_sync(sense);

    // ph2: top scan of the 98 chunk totals (CTA 0 only)
    if (cta == 0) {
        int* tops = (int*)smem_raw;
        int tv = 0;
        if (tid < 128) {
            tv = (tid < NBLK_SCAN) ? g_blocksum[tid] : 0;
            tops[tid] = tv;
        }
        __syncthreads();
#pragma unroll
        for (int off = 1; off < 128; off <<= 1) {
            int t2 = 0;
            if (tid < 128 && tid >= off) t2 = tops[tid - off];
            __syncthreads();
            if (tid < 128) tops[tid] += t2;
            __syncthreads();
        }
        if (tid < NBLK_SCAN) g_blocksum[tid] = tops[tid] - tv;   // exclusive
    }
    grid_sync(sense);

    // ph3: scatter edges into CSR
    for (int e = cta * NTHREAD + tid; e < N_EDGES; e += NCTA * NTHREAD) {
        int d = edge_dst[e];
        int pos = g_rowptr[d] + g_blocksum[d >> 9] + atomicAdd(&g_cursor[d], 1);
        reinterpret_cast<int2*>(g_csr_ew)[pos] =
            make_int2(edge_src[e], __float_as_int(edge_w[e]));
    }
    grid_sync(sense);

    // layer 0 aggregate
    spmm_phase<128, true>(g_support, b0, g_h);
    grid_sync(sense);
    // layer 1
    for (int t = cta; t < NB_GEMM_C; t += NCTA)
        gemm_body<128>(g_h, W1, g_support, N_NODES, t, smem_raw);
    grid_sync(sense);
    spmm_phase<128, true>(g_support, b1, g_h);
    grid_sync(sense);
    // layer 2
    for (int t = cta; t < NB_GEMM_C; t += NCTA)
        gemm_body<128>(g_h, W2, g_support, N_NODES, t, smem_raw);
    grid_sync(sense);
    spmm_phase<128, true>(g_support, b2, g_h);
    grid_sync(sense);
    // layer 3 (d=64, no relu)
    for (int t = cta; t < NB_GEMM_C; t += NCTA)
        gemm_body<64>(g_h, W3, g_support, N_NODES, t, smem_raw);
    grid_sync(sense);
    spmm_phase<64, false>(g_support, b3, out);
}

// ---------------- launch ----------------
extern "C" void kernel_launch(void* const* d_in, const int* in_sizes, int n_in,
                              void* d_out, int out_size) {
    const float* x        = (const float*)d_in[0];
    const int*   edge_src = (const int*)  d_in[1];
    const int*   edge_dst = (const int*)  d_in[2];
    const float* edge_w   = (const float*)d_in[3];
    const float* W0 = (const float*)d_in[4];  const float* b0 = (const float*)d_in[5];
    const float* W1 = (const float*)d_in[6];  const float* b1 = (const float*)d_in[7];
    const float* W2 = (const float*)d_in[8];  const float* b2 = (const float*)d_in[9];
    const float* W3 = (const float*)d_in[10]; const float* b3 = (const float*)d_in[11];
    float* out = (float*)d_out;

    int* cursor; cudaGetSymbolAddress((void**)&cursor, g_cursor);
    int* bar;    cudaGetSymbolAddress((void**)&bar, g_bar);

    cudaMemsetAsync(cursor, 0, N_NODES * sizeof(int), 0);
    cudaMemsetAsync(bar, 0, 2 * sizeof(int), 0);

    persistent_kernel<<<NCTA, NTHREAD>>>(x, edge_src, edge_dst, edge_w,
                                         W0, b0, W1, b1, W2, b2, W3, b3, out);
}

// round 15
// speedup vs baseline: 1.4373x; 1.4373x over previous
#include <cuda_runtime.h>
#include <cuda_bf16.h>

#define N_NODES 50000
#define N_EDGES 800000
#define NFEAT 128
#define NHID 128
#define NOUT 64

#define NB_GEMM_C ((N_NODES + 127) / 128)     // 391
#define NB_EDGE_C ((N_EDGES + 255) / 256)     // 3125
#define NBLK_SCAN ((N_NODES + 511) / 512)     // 98

// ---------------- scratch (static __device__, no allocations) ----------------
__device__ __align__(16) __nv_bfloat16 g_support[N_NODES * 128];  // bf16 support
__device__ __align__(16) float g_h[N_NODES * 128];
__device__ int   g_rowptr[N_NODES + 1];       // chunk-LOCAL exclusive prefix
__device__ int   g_cursor[N_NODES];
__device__ int   g_blocksum[128];             // exclusive chunk offsets
__device__ int   g_scan_done;
__device__ __align__(16) int g_csr_ew[N_EDGES * 2];   // interleaved {src, w_bits}

// ---------------- helpers ----------------
__device__ __forceinline__ void ffma2(unsigned long long& d,
                                      unsigned long long a,
                                      unsigned long long b) {
    asm("fma.rn.f32x2 %0, %1, %2, %0;" : "+l"(d) : "l"(a), "l"(b));
}
__device__ __forceinline__ unsigned long long dup2(float x) {
    unsigned long long r;
    asm("mov.b64 %0, {%1, %1};" : "=l"(r) : "f"(x));
    return r;
}
__device__ __forceinline__ unsigned cvt_bf2(unsigned long long pair) {
    float lo, hi; unsigned r;
    asm("mov.b64 {%0, %1}, %2;" : "=f"(lo), "=f"(hi) : "l"(pair));
    asm("cvt.rn.bf16x2.f32 %0, %1, %2;" : "=r"(r) : "f"(hi), "f"(lo));
    return r;
}
__device__ __forceinline__ float2 bf2f(unsigned bits) {
    __nv_bfloat162 h = *reinterpret_cast<const __nv_bfloat162*>(&bits);
    return __bfloat1622float2(h);
}
// PDL entry: release our secondary ASAP, then wait for our primary.
__device__ __forceinline__ void pdl_entry() {
    cudaTriggerProgrammaticLaunchCompletion();
    cudaGridDependencySynchronize();
}

// ---------------- GEMM body: C[M,BN](bf16) = A[M,128](f32) @ B[128,BN](f32)
// BM=128, BK=16, double-buffered smem (48 KB), 256 threads, FFMA2 math,
// bf16x2 epilogue.
template <int BN>
__device__ __forceinline__ void gemm_body(const float* __restrict__ A,
                                          const float* __restrict__ B,
                                          __nv_bfloat16* __restrict__ C,
                                          int M, int block) {
    constexpr int K = 128, BM = 128, BK = 16;
    constexpr int TM = 8, TN = BN / 16, TN2 = TN / 2;
    constexpr int NSLAB = K / BK;                 // 8
    constexpr int A_IT = (BM * BK / 4) / 256;     // 2
    constexpr int B_IT = (BK * BN / 4) / 256;     // 2 (BN=128) / 1 (BN=64)

    __shared__ unsigned long long As2[2][BK][BM]; // 2 x 16 KB, {a,a} pairs
    __shared__ float Bs[2][BK][BN];               // 2 x 8/4 KB

    const int tid = threadIdx.x;
    const int m0  = block * BM;
    const int tx  = tid % 16;
    const int ty  = tid / 16;
    const int mm  = ty * TM;
    const int nn  = tx * TN;

    unsigned long long acc2[TM][TN2];
#pragma unroll
    for (int i = 0; i < TM; i++)
#pragma unroll
        for (int j = 0; j < TN2; j++) acc2[i][j] = 0ull;

    const float4* A4 = reinterpret_cast<const float4*>(A);
    const float4* B4 = reinterpret_cast<const float4*>(B);

    float4 areg[A_IT], breg[B_IT];

    auto load_global = [&](int s) {
#pragma unroll
        for (int it = 0; it < A_IT; it++) {
            int f  = tid + it * 256;
            int m  = f & (BM - 1);
            int kq = f >> 7;                       // 0..BK/4-1
            int gm = m0 + m;
            areg[it] = (gm < M) ? A4[gm * (K / 4) + (s * BK) / 4 + kq]
                                : make_float4(0.f, 0.f, 0.f, 0.f);
        }
#pragma unroll
        for (int it = 0; it < B_IT; it++) {
            int f = tid + it * 256;
            breg[it] = B4[(s * BK) * (BN / 4) + f];
        }
    };
    auto store_smem = [&](int buf) {
#pragma unroll
        for (int it = 0; it < A_IT; it++) {
            int f  = tid + it * 256;
            int m  = f & (BM - 1);
            int k  = (f >> 7) * 4;
            As2[buf][k + 0][m] = dup2(areg[it].x);
            As2[buf][k + 1][m] = dup2(areg[it].y);
            As2[buf][k + 2][m] = dup2(areg[it].z);
            As2[buf][k + 3][m] = dup2(areg[it].w);
        }
#pragma unroll
        for (int it = 0; it < B_IT; it++) {
            int f = tid + it * 256;
            reinterpret_cast<float4*>(&Bs[buf][0][0])[f] = breg[it];
        }
    };
    auto compute = [&](int buf) {
#pragma unroll
        for (int k = 0; k < BK; k++) {
            unsigned long long a2[TM];
#pragma unroll
            for (int i2 = 0; i2 < TM / 2; i2++) {
                ulonglong2 av = *reinterpret_cast<const ulonglong2*>(&As2[buf][k][mm + i2 * 2]);
                a2[i2 * 2 + 0] = av.x;
                a2[i2 * 2 + 1] = av.y;
            }
            unsigned long long b2[TN2];
#pragma unroll
            for (int j4 = 0; j4 < TN2 / 2; j4++) {
                ulonglong2 bv = *reinterpret_cast<const ulonglong2*>(&Bs[buf][k][nn + j4 * 4]);
                b2[j4 * 2 + 0] = bv.x;
                b2[j4 * 2 + 1] = bv.y;
            }
#pragma unroll
            for (int i = 0; i < TM; i++)
#pragma unroll
                for (int j = 0; j < TN2; j++) ffma2(acc2[i][j], a2[i], b2[j]);
        }
    };

    load_global(0);
    store_smem(0);
    __syncthreads();

    for (int s = 0; s < NSLAB; s++) {
        int cur = s & 1;
        bool has_next = (s + 1) < NSLAB;
        if (has_next) load_global(s + 1);   // LDG latency hidden by compute
        compute(cur);
        if (has_next) store_smem(cur ^ 1);
        __syncthreads();
    }

    // epilogue: pack each f32 pair -> bf16x2, vector store
#pragma unroll
    for (int i = 0; i < TM; i++) {
        int row = m0 + mm + i;
        if (row < M) {
            unsigned r32[TN2];
#pragma unroll
            for (int j = 0; j < TN2; j++) r32[j] = cvt_bf2(acc2[i][j]);
            unsigned* outp = reinterpret_cast<unsigned*>(C + row * BN + nn);
            if constexpr (TN2 == 4) {
                uint4 o = make_uint4(r32[0], r32[1], r32[2], r32[3]);
                *reinterpret_cast<uint4*>(outp) = o;
            } else {
                uint2 o = make_uint2(r32[0], r32[1]);
                *reinterpret_cast<uint2*>(outp) = o;
            }
        }
    }
}

template <int BN>
__global__ void __launch_bounds__(256)
gemm_kernel(const float* __restrict__ A, const float* __restrict__ B,
            __nv_bfloat16* __restrict__ C, int M) {
    pdl_entry();
    gemm_body<BN>(A, B, C, M, blockIdx.x);
}

// ---------------- fused: gemm0 tiles + edge histogram in one grid ----------------
__global__ void __launch_bounds__(256)
gemm0_hist_kernel(const float* __restrict__ A, const float* __restrict__ B,
                  __nv_bfloat16* __restrict__ C,
                  const int* __restrict__ dst) {
    cudaTriggerProgrammaticLaunchCompletion();   // release scan's launch early
    if (blockIdx.x >= NB_GEMM_C) {
        // histogram part (runs concurrently with gemm0 tiles)
        int e = (blockIdx.x - NB_GEMM_C) * 256 + (int)threadIdx.x;
        if (e < N_EDGES) atomicAdd(&g_cursor[dst[e]], 1);
        if (blockIdx.x == NB_GEMM_C && threadIdx.x == 0) g_scan_done = 0;
        return;
    }
    gemm_body<128>(A, B, C, N_NODES, blockIdx.x);
}

// ---------------- scan (single kernel, last-block-ticket top scan) ----------------
__global__ void scan_blocks_kernel() {
    pdl_entry();
    __shared__ int sdata[512];
    __shared__ int flag;
    __shared__ int tops[128];
    const int tid = threadIdx.x;
    int i = blockIdx.x * 512 + tid;
    int v = (i < N_NODES) ? g_cursor[i] : 0;
    if (i < N_NODES) g_cursor[i] = 0;         // re-zero for scatter pass
    sdata[tid] = v;
    __syncthreads();
#pragma unroll
    for (int off = 1; off < 512; off <<= 1) {
        int t = (tid >= off) ? sdata[tid - off] : 0;
        __syncthreads();
        sdata[tid] += t;
        __syncthreads();
    }
    if (i <= N_NODES) g_rowptr[i] = sdata[tid] - v;   // chunk-local exclusive
    if (tid == 511) {
        g_blocksum[blockIdx.x] = sdata[511];          // chunk total
        __threadfence();                              // publish before ticket
        int t = atomicAdd(&g_scan_done, 1);
        flag = (t == NBLK_SCAN - 1) ? 1 : 0;
    }
    __syncthreads();
    if (flag) {                                       // last block: top scan
        int tv = 0;
        if (tid < 128) {
            tv = (tid < NBLK_SCAN) ? *((volatile int*)&g_blocksum[tid]) : 0;
            tops[tid] = tv;
        }
        __syncthreads();
        for (int off = 1; off < 128; off <<= 1) {
            int t2 = 0;
            if (tid < 128 && tid >= off) t2 = tops[tid - off];
            __syncthreads();
            if (tid < 128) tops[tid] += t2;
            __syncthreads();
        }
        if (tid < NBLK_SCAN) g_blocksum[tid] = tops[tid] - tv;  // exclusive
    }
}

__global__ void scatter_kernel(const int* __restrict__ src,
                               const int* __restrict__ dst,
                               const float* __restrict__ w) {
    pdl_entry();
    int e = blockIdx.x * blockDim.x + threadIdx.x;
    if (e < N_EDGES) {
        int d = dst[e];
        int pos = g_rowptr[d] + g_blocksum[d >> 9] + atomicAdd(&g_cursor[d], 1);
        reinterpret_cast<int2*>(g_csr_ew)[pos] =
            make_int2(src[e], __float_as_int(w[e]));
    }
}

// ---------------- SpMM (CSR-by-dst, bf16 gather, packed edges) ----------------
// one warp per destination node; lane owns D/32 consecutive channels.
template <int D, bool RELU>
__global__ void spmm_kernel(const __nv_bfloat16* __restrict__ sup,
                            const float* __restrict__ bias,
                            float* __restrict__ out) {
    pdl_entry();
    int gw = (blockIdx.x * blockDim.x + threadIdx.x) >> 5;
    if (gw >= N_NODES) return;
    int lane = threadIdx.x & 31;
    int s = g_rowptr[gw]     + g_blocksum[gw >> 9];
    int e = g_rowptr[gw + 1] + g_blocksum[(gw + 1) >> 9];

    const int4* ew4 = reinterpret_cast<const int4*>(g_csr_ew);  // 2 edges each
    const int2* ew2 = reinterpret_cast<const int2*>(g_csr_ew);  // 1 edge each

    if constexpr (D == 128) {
        const uint2* supv = reinterpret_cast<const uint2*>(sup);  // 32 uint2/row
        float4 acc = make_float4(0.f, 0.f, 0.f, 0.f);
        int i = s;

        auto edge = [&](int sn, float wn) {
            uint2 v = supv[sn * 32 + lane];
            float2 p;
            p = bf2f(v.x); acc.x += wn * p.x; acc.y += wn * p.y;
            p = bf2f(v.y); acc.z += wn * p.x; acc.w += wn * p.y;
        };

        if (i < e && (i & 1)) {               // align to int4 boundary
            int2 p = ew2[i];
            edge(p.x, __int_as_float(p.y));
            i++;
        }
        for (; i + 3 < e; i += 4) {           // 4 edges: 2 LDG.128 + 4 gathers
            int4 pa = ew4[i >> 1];
            int4 pb = ew4[(i >> 1) + 1];
            uint2 v0 = supv[pa.x * 32 + lane];
            uint2 v1 = supv[pa.z * 32 + lane];
            uint2 v2 = supv[pb.x * 32 + lane];
            uint2 v3 = supv[pb.z * 32 + lane];
            float w0 = __int_as_float(pa.y), w1 = __int_as_float(pa.w);
            float w2 = __int_as_float(pb.y), w3 = __int_as_float(pb.w);
            float2 p;
            p = bf2f(v0.x); acc.x += w0 * p.x; acc.y += w0 * p.y;
            p = bf2f(v0.y); acc.z += w0 * p.x; acc.w += w0 * p.y;
            p = bf2f(v1.x); acc.x += w1 * p.x; acc.y += w1 * p.y;
            p = bf2f(v1.y); acc.z += w1 * p.x; acc.w += w1 * p.y;
            p = bf2f(v2.x); acc.x += w2 * p.x; acc.y += w2 * p.y;
            p = bf2f(v2.y); acc.z += w2 * p.x; acc.w += w2 * p.y;
            p = bf2f(v3.x); acc.x += w3 * p.x; acc.y += w3 * p.y;
            p = bf2f(v3.y); acc.z += w3 * p.x; acc.w += w3 * p.y;
        }
        for (; i + 1 < e; i += 2) {
            int4 pa = ew4[i >> 1];
            edge(pa.x, __int_as_float(pa.y));
            edge(pa.z, __int_as_float(pa.w));
        }
        if (i < e) {
            int2 p = ew2[i];
            edge(p.x, __int_as_float(p.y));
        }

        float4 b = reinterpret_cast<const float4*>(bias)[lane];
        acc.x += b.x; acc.y += b.y; acc.z += b.z; acc.w += b.w;
        if (RELU) {
            acc.x = fmaxf(acc.x, 0.f); acc.y = fmaxf(acc.y, 0.f);
            acc.z = fmaxf(acc.z, 0.f); acc.w = fmaxf(acc.w, 0.f);
        }
        reinterpret_cast<float4*>(out)[gw * 32 + lane] = acc;
    } else {  // D == 64
        const unsigned* supv = reinterpret_cast<const unsigned*>(sup);  // 32 u32/row
        float2 acc = make_float2(0.f, 0.f);
        int i = s;

        auto edge = [&](int sn, float wn) {
            float2 p = bf2f(supv[sn * 32 + lane]);
            acc.x += wn * p.x; acc.y += wn * p.y;
        };

        if (i < e && (i & 1)) {
            int2 p = ew2[i];
            edge(p.x, __int_as_float(p.y));
            i++;
        }
        for (; i + 3 < e; i += 4) {
            int4 pa = ew4[i >> 1];
            int4 pb = ew4[(i >> 1) + 1];
            unsigned v0 = supv[pa.x * 32 + lane];
            unsigned v1 = supv[pa.z * 32 + lane];
            unsigned v2 = supv[pb.x * 32 + lane];
            unsigned v3 = supv[pb.z * 32 + lane];
            float w0 = __int_as_float(pa.y), w1 = __int_as_float(pa.w);
            float w2 = __int_as_float(pb.y), w3 = __int_as_float(pb.w);
            float2 p;
            p = bf2f(v0); acc.x += w0 * p.x; acc.y += w0 * p.y;
            p = bf2f(v1); acc.x += w1 * p.x; acc.y += w1 * p.y;
            p = bf2f(v2); acc.x += w2 * p.x; acc.y += w2 * p.y;
            p = bf2f(v3); acc.x += w3 * p.x; acc.y += w3 * p.y;
        }
        for (; i + 1 < e; i += 2) {
            int4 pa = ew4[i >> 1];
            edge(pa.x, __int_as_float(pa.y));
            edge(pa.z, __int_as_float(pa.w));
        }
        if (i < e) {
            int2 p = ew2[i];
            edge(p.x, __int_as_float(p.y));
        }

        float2 b = reinterpret_cast<const float2*>(bias)[lane];
        acc.x += b.x; acc.y += b.y;
        if (RELU) { acc.x = fmaxf(acc.x, 0.f); acc.y = fmaxf(acc.y, 0.f); }
        reinterpret_cast<float2*>(out)[gw * 32 + lane] = acc;
    }
}

// ---------------- host-side PDL launch helper ----------------
template <typename F, typename... Args>
static void pdl_launch(F f, dim3 grid, dim3 block, Args... args) {
    cudaLaunchConfig_t cfg = {};
    cudaLaunchAttribute at;
    at.id = cudaLaunchAttributeProgrammaticStreamSerialization;
    at.val.programmaticStreamSerializationAllowed = 1;
    cfg.gridDim = grid;
    cfg.blockDim = block;
    cfg.dynamicSmemBytes = 0;
    cfg.stream = 0;
    cfg.attrs = &at;
    cfg.numAttrs = 1;
    cudaLaunchKernelEx(&cfg, f, args...);
}

// ---------------- launch (single stream + PDL chaining) ----------------
extern "C" void kernel_launch(void* const* d_in, const int* in_sizes, int n_in,
                              void* d_out, int out_size) {
    const float* x        = (const float*)d_in[0];
    const int*   edge_src = (const int*)  d_in[1];
    const int*   edge_dst = (const int*)  d_in[2];
    const float* edge_w   = (const float*)d_in[3];
    const float* W0 = (const float*)d_in[4];  const float* b0 = (const float*)d_in[5];
    const float* W1 = (const float*)d_in[6];  const float* b1 = (const float*)d_in[7];
    const float* W2 = (const float*)d_in[8];  const float* b2 = (const float*)d_in[9];
    const float* W3 = (const float*)d_in[10]; const float* b3 = (const float*)d_in[11];
    float* out = (float*)d_out;

    __nv_bfloat16* support; cudaGetSymbolAddress((void**)&support, g_support);
    float* h;               cudaGetSymbolAddress((void**)&h, g_h);
    int*   cursor;          cudaGetSymbolAddress((void**)&cursor, g_cursor);

    const int NB_SPMM = (N_NODES + 7) / 8;      // 8 warps/block

    cudaMemsetAsync(cursor, 0, N_NODES * sizeof(int), 0);

    // layer-0 GEMM fused with edge histogram (plain launch; first kernel)
    gemm0_hist_kernel<<<NB_GEMM_C + NB_EDGE_C, 256>>>(x, W0, support, edge_dst);

    // CSR: scan + scatter, PDL-chained
    pdl_launch(scan_blocks_kernel, dim3(NBLK_SCAN), dim3(512));
    pdl_launch(scatter_kernel, dim3(NB_EDGE_C), dim3(256),
               edge_src, edge_dst, edge_w);

    // layer 0 aggregate
    pdl_launch(spmm_kernel<128, true>, dim3(NB_SPMM), dim3(256),
               (const __nv_bfloat16*)support, b0, h);
    // layer 1
    pdl_launch(gemm_kernel<128>, dim3(NB_GEMM_C), dim3(256),
               (const float*)h, W1, support, (int)N_NODES);
    pdl_launch(spmm_kernel<128, true>, dim3(NB_SPMM), dim3(256),
               (const __nv_bfloat16*)support, b1, h);
    // layer 2
    pdl_launch(gemm_kernel<128>, dim3(NB_GEMM_C), dim3(256),
               (const float*)h, W2, support, (int)N_NODES);
    pdl_launch(spmm_kernel<128, true>, dim3(NB_SPMM), dim3(256),
               (const __nv_bfloat16*)support, b2, h);
    // layer 3 (d=64, no relu) -> d_out
    pdl_launch(gemm_kernel<64>, dim3(NB_GEMM_C), dim3(256),
               (const float*)h, W3, support, (int)N_NODES);
    pdl_launch(spmm_kernel<64, false>, dim3(NB_SPMM), dim3(256),
               (const __nv_bfloat16*)support, b3, out);
}

// round 17
// speedup vs baseline: 1.8461x; 1.2844x over previous
#include <cuda_runtime.h>
#include <cuda_bf16.h>
#include <cstdint>

#define N_NODES 50000
#define N_EDGES 800000
#define NFEAT 128
#define NHID 128
#define NOUT 64

#define NB_GEMM_C ((N_NODES + 127) / 128)     // 391
#define NB_EDGE_C ((N_EDGES + 255) / 256)     // 3125
#define NBLK_SCAN ((N_NODES + 511) / 512)     // 98
#define EPC ((N_EDGES + NB_GEMM_C - 1) / NB_GEMM_C)   // edges per gemm0 CTA

// ---------------- scratch (static __device__, no allocations) ----------------
__device__ __align__(16) __nv_bfloat16 g_support[N_NODES * 128];  // bf16 support
__device__ __align__(16) float g_h[N_NODES * 128];
__device__ int   g_rowptr[N_NODES + 1];       // chunk-LOCAL exclusive prefix
__device__ int   g_cursor[N_NODES];
__device__ int   g_blocksum[128];             // exclusive chunk offsets
__device__ int   g_scan_done;
__device__ __align__(16) int g_csr_ew[N_EDGES * 2];   // interleaved {src, w_bits}
// transposed weight images, hi/lo bf16 split, padded rows:
// per n-row: [chunk0: 64k = 128B + 16B pad][chunk1: same] = 288 B.
// bases: L0=0, L1=36864, L2=73728, L3=110592; total 129024 B.
__device__ __align__(16) unsigned char g_wimg_hi[129024];
__device__ __align__(16) unsigned char g_wimg_lo[129024];

// ---------------- tiny helpers ----------------
__device__ __forceinline__ float2 bf2f(unsigned bits) {
    __nv_bfloat162 h = *reinterpret_cast<const __nv_bfloat162*>(&bits);
    return __bfloat1622float2(h);
}
__device__ __forceinline__ unsigned pack_bf2(float lo, float hi) {
    unsigned r;
    asm("cvt.rn.bf16x2.f32 %0, %1, %2;" : "=r"(r) : "f"(hi), "f"(lo));
    return r;
}
__device__ __forceinline__ void pdl_entry() {
    cudaTriggerProgrammaticLaunchCompletion();
    cudaGridDependencySynchronize();
}
// m16n8k16 bf16 HMMA, fp32 accumulate (baseline PTX, sm_80+; OK on compute_103)
__device__ __forceinline__ void mma_bf16(float* c, const uint32_t* a,
                                         const uint32_t* b) {
    asm volatile(
        "mma.sync.aligned.m16n8k16.row.col.f32.bf16.bf16.f32 "
        "{%0,%1,%2,%3}, {%4,%5,%6,%7}, {%8,%9}, {%0,%1,%2,%3};"
        : "+f"(c[0]), "+f"(c[1]), "+f"(c[2]), "+f"(c[3])
        : "r"(a[0]), "r"(a[1]), "r"(a[2]), "r"(a[3]), "r"(b[0]), "r"(b[1]));
}

// ---------------- weight prep: transpose + hi/lo split + padded image -------
__global__ void prep_weights_kernel(const float* __restrict__ W0,
                                    const float* __restrict__ W1,
                                    const float* __restrict__ W2,
                                    const float* __restrict__ W3) {
    int idx = blockIdx.x * 256 + threadIdx.x;     // < 57344
    if (idx >= 57344) return;
    const float* W; int i, Nl, lb;
    if (idx < 49152) {
        int l = idx / 16384;
        W = (l == 0) ? W0 : (l == 1) ? W1 : W2;
        i = idx - l * 16384; Nl = 128; lb = l * 36864;
    } else {
        W = W3; i = idx - 49152; Nl = 64; lb = 110592;
    }
    int n = i % Nl, k = i / Nl;                   // W[k][n], coalesced read
    float w = W[i];
    __nv_bfloat16 hb = __float2bfloat16(w);
    float lof = w - __bfloat162float(hb);
    __nv_bfloat16 lo = __float2bfloat16(lof);
    int off = lb + n * 288 + (k >> 6) * 144 + (k & 63) * 2;
    *reinterpret_cast<__nv_bfloat16*>(g_wimg_hi + off) = hb;
    *reinterpret_cast<__nv_bfloat16*>(g_wimg_lo + off) = lo;
}

// ---------------- HMMA GEMM: C[M,BN](bf16) = A[M,128](f32) @ W --------------
// split-bf16 3-pass (AhiBhi + AhiBlo + AloBhi), fp32 accum in registers.
// BM=128, 256 thr, warp grid 4x2 (each warp 32 x BN/2). 2 K-chunks of 64.
// smem rows padded to 144 B -> conflict-free 32-bit fragment LDS.
template <int BN, bool FUSE_HIST>
__global__ void __launch_bounds__(256, 2)
mma_gemm_kernel(const float* __restrict__ A,
                const unsigned char* __restrict__ wimg_hi,
                const unsigned char* __restrict__ wimg_lo,
                __nv_bfloat16* __restrict__ C,
                const int* __restrict__ dst) {
    constexpr int NT = BN / 16;                   // n-tiles per warp (8 / 4)
    constexpr int A_HI = 0;
    constexpr int A_LO = 128 * 144;               // 18432
    constexpr int W_HI = 2 * 128 * 144;           // 36864
    constexpr int W_LO = W_HI + BN * 144;

    extern __shared__ __align__(16) unsigned char smem[];
    const int tid  = threadIdx.x;
    const int wid  = tid >> 5;
    const int lane = tid & 31;
    const int g    = lane >> 2;                   // 0..7
    const int tg   = lane & 3;                    // 0..3
    const int wr   = wid & 3;                     // warp row (32 rows)
    const int wc   = wid >> 2;                    // warp col half
    const int m0   = blockIdx.x * 128;

    pdl_entry();

    if (FUSE_HIST) {
        int e0 = blockIdx.x * EPC;
        int e1 = min(e0 + EPC, N_EDGES);
        for (int e = e0 + tid; e < e1; e += 256)
            atomicAdd(&g_cursor[dst[e]], 1);
        if (blockIdx.x == 0 && tid == 0) g_scan_done = 0;
    }

    float acc[2][NT][4];
#pragma unroll
    for (int tm = 0; tm < 2; tm++)
#pragma unroll
        for (int tn = 0; tn < NT; tn++)
#pragma unroll
            for (int j = 0; j < 4; j++) acc[tm][tn][j] = 0.f;

    for (int c = 0; c < 2; c++) {
        // ---- stage A chunk (fp32 -> hi/lo bf16), rows padded to 144 B ----
        {
            int row  = tid >> 1;
            int half = tid & 1;
            int gm   = m0 + row;
            bool ok  = gm < N_NODES;
            const float4* A4 = reinterpret_cast<const float4*>(A);
            int gbase = row < 128 ? (gm * 32 + c * 16 + half * 8) : 0;
#pragma unroll
            for (int j = 0; j < 8; j++) {
                float4 v = ok ? A4[gbase + j] : make_float4(0.f, 0.f, 0.f, 0.f);
                __nv_bfloat16 h0 = __float2bfloat16(v.x);
                __nv_bfloat16 h1 = __float2bfloat16(v.y);
                __nv_bfloat16 h2 = __float2bfloat16(v.z);
                __nv_bfloat16 h3 = __float2bfloat16(v.w);
                unsigned hw0 = pack_bf2(__bfloat162float(h0), __bfloat162float(h1));
                unsigned hw1 = pack_bf2(__bfloat162float(h2), __bfloat162float(h3));
                unsigned lw0 = pack_bf2(v.x - __bfloat162float(h0),
                                        v.y - __bfloat162float(h1));
                unsigned lw1 = pack_bf2(v.z - __bfloat162float(h2),
                                        v.w - __bfloat162float(h3));
                uint32_t off = (uint32_t)(row * 144 + half * 64 + j * 8);
                *reinterpret_cast<uint2*>(smem + A_HI + off) = make_uint2(hw0, hw1);
                *reinterpret_cast<uint2*>(smem + A_LO + off) = make_uint2(lw0, lw1);
            }
        }
        // ---- stage W chunk: uint4 copy of padded global image ----
        {
            constexpr int NROWQ = BN * 9;          // uint4 per chunk
            for (int i = tid; i < NROWQ; i += 256) {
                int row = i / 9, q = i % 9;
                uint32_t doff = (uint32_t)(row * 144 + q * 16);
                uint32_t soff = (uint32_t)(row * 288 + c * 144 + q * 16);
                *reinterpret_cast<uint4*>(smem + W_HI + doff) =
                    *reinterpret_cast<const uint4*>(wimg_hi + soff);
                *reinterpret_cast<uint4*>(smem + W_LO + doff) =
                    *reinterpret_cast<const uint4*>(wimg_lo + soff);
            }
        }
        __syncthreads();

        // ---- compute: 4 k-steps of 16 ----
#pragma unroll
        for (int ks = 0; ks < 4; ks++) {
            int kb = ks * 32 + tg * 4;            // byte offset within row
            uint32_t ah[2][4], al[2][4];
#pragma unroll
            for (int tm = 0; tm < 2; tm++) {
                uint32_t r0 = (uint32_t)((wr * 32 + tm * 16 + g) * 144 + kb);
                ah[tm][0] = *reinterpret_cast<const uint32_t*>(smem + A_HI + r0);
                ah[tm][1] = *reinterpret_cast<const uint32_t*>(smem + A_HI + r0 + 8 * 144);
                ah[tm][2] = *reinterpret_cast<const uint32_t*>(smem + A_HI + r0 + 16);
                ah[tm][3] = *reinterpret_cast<const uint32_t*>(smem + A_HI + r0 + 8 * 144 + 16);
                al[tm][0] = *reinterpret_cast<const uint32_t*>(smem + A_LO + r0);
                al[tm][1] = *reinterpret_cast<const uint32_t*>(smem + A_LO + r0 + 8 * 144);
                al[tm][2] = *reinterpret_cast<const uint32_t*>(smem + A_LO + r0 + 16);
                al[tm][3] = *reinterpret_cast<const uint32_t*>(smem + A_LO + r0 + 8 * 144 + 16);
            }
#pragma unroll
            for (int tn = 0; tn < NT; tn++) {
                uint32_t n0 = (uint32_t)((wc * (BN / 2) + tn * 8 + g) * 144 + kb);
                uint32_t bh[2], bl[2];
                bh[0] = *reinterpret_cast<const uint32_t*>(smem + W_HI + n0);
                bh[1] = *reinterpret_cast<const uint32_t*>(smem + W_HI + n0 + 16);
                bl[0] = *reinterpret_cast<const uint32_t*>(smem + W_LO + n0);
                bl[1] = *reinterpret_cast<const uint32_t*>(smem + W_LO + n0 + 16);
#pragma unroll
                for (int tm = 0; tm < 2; tm++) {
                    mma_bf16(acc[tm][tn], ah[tm], bh);
                    mma_bf16(acc[tm][tn], ah[tm], bl);
                    mma_bf16(acc[tm][tn], al[tm], bh);
                }
            }
        }
        __syncthreads();
    }

    // ---- epilogue: pack fp32 pairs -> bf16x2, direct STG ----
#pragma unroll
    for (int tm = 0; tm < 2; tm++) {
        int row0 = m0 + wr * 32 + tm * 16 + g;
        int row1 = row0 + 8;
#pragma unroll
        for (int tn = 0; tn < NT; tn++) {
            int col = wc * (BN / 2) + tn * 8 + tg * 2;
            if (row0 < N_NODES)
                *reinterpret_cast<unsigned*>(C + row0 * BN + col) =
                    pack_bf2(acc[tm][tn][0], acc[tm][tn][1]);
            if (row1 < N_NODES)
                *reinterpret_cast<unsigned*>(C + row1 * BN + col) =
                    pack_bf2(acc[tm][tn][2], acc[tm][tn][3]);
        }
    }
}

// ---------------- scan (single kernel, last-block-ticket top scan) ----------
__global__ void scan_blocks_kernel() {
    pdl_entry();
    __shared__ int sdata[512];
    __shared__ int flag;
    __shared__ int tops[128];
    const int tid = threadIdx.x;
    int i = blockIdx.x * 512 + tid;
    int v = (i < N_NODES) ? g_cursor[i] : 0;
    if (i < N_NODES) g_cursor[i] = 0;         // re-zero for scatter pass
    sdata[tid] = v;
    __syncthreads();
#pragma unroll
    for (int off = 1; off < 512; off <<= 1) {
        int t = (tid >= off) ? sdata[tid - off] : 0;
        __syncthreads();
        sdata[tid] += t;
        __syncthreads();
    }
    if (i <= N_NODES) g_rowptr[i] = sdata[tid] - v;   // chunk-local exclusive
    if (tid == 511) {
        g_blocksum[blockIdx.x] = sdata[511];          // chunk total
        __threadfence();                              // publish before ticket
        int t = atomicAdd(&g_scan_done, 1);
        flag = (t == NBLK_SCAN - 1) ? 1 : 0;
    }
    __syncthreads();
    if (flag) {                                       // last block: top scan
        int tv = 0;
        if (tid < 128) {
            tv = (tid < NBLK_SCAN) ? *((volatile int*)&g_blocksum[tid]) : 0;
            tops[tid] = tv;
        }
        __syncthreads();
        for (int off = 1; off < 128; off <<= 1) {
            int t2 = 0;
            if (tid < 128 && tid >= off) t2 = tops[tid - off];
            __syncthreads();
            if (tid < 128) tops[tid] += t2;
            __syncthreads();
        }
        if (tid < NBLK_SCAN) g_blocksum[tid] = tops[tid] - tv;  // exclusive
    }
}

__global__ void scatter_kernel(const int* __restrict__ src,
                               const int* __restrict__ dst,
                               const float* __restrict__ w) {
    pdl_entry();
    int e = blockIdx.x * blockDim.x + threadIdx.x;
    if (e < N_EDGES) {
        int d = dst[e];
        int pos = g_rowptr[d] + g_blocksum[d >> 9] + atomicAdd(&g_cursor[d], 1);
        reinterpret_cast<int2*>(g_csr_ew)[pos] =
            make_int2(src[e], __float_as_int(w[e]));
    }
}

// ---------------- SpMM (CSR-by-dst, bf16 gather, packed edges) ----------------
template <int D, bool RELU>
__global__ void spmm_kernel(const __nv_bfloat16* __restrict__ sup,
                            const float* __restrict__ bias,
                            float* __restrict__ out) {
    pdl_entry();
    int gw = (blockIdx.x * blockDim.x + threadIdx.x) >> 5;
    if (gw >= N_NODES) return;
    int lane = threadIdx.x & 31;
    int s = g_rowptr[gw]     + g_blocksum[gw >> 9];
    int e = g_rowptr[gw + 1] + g_blocksum[(gw + 1) >> 9];

    const int4* ew4 = reinterpret_cast<const int4*>(g_csr_ew);
    const int2* ew2 = reinterpret_cast<const int2*>(g_csr_ew);

    if constexpr (D == 128) {
        const uint2* supv = reinterpret_cast<const uint2*>(sup);
        float4 acc = make_float4(0.f, 0.f, 0.f, 0.f);
        int i = s;

        auto edge = [&](int sn, float wn) {
            uint2 v = supv[sn * 32 + lane];
            float2 p;
            p = bf2f(v.x); acc.x += wn * p.x; acc.y += wn * p.y;
            p = bf2f(v.y); acc.z += wn * p.x; acc.w += wn * p.y;
        };

        if (i < e && (i & 1)) { int2 p = ew2[i]; edge(p.x, __int_as_float(p.y)); i++; }
        for (; i + 3 < e; i += 4) {
            int4 pa = ew4[i >> 1];
            int4 pb = ew4[(i >> 1) + 1];
            uint2 v0 = supv[pa.x * 32 + lane];
            uint2 v1 = supv[pa.z * 32 + lane];
            uint2 v2 = supv[pb.x * 32 + lane];
            uint2 v3 = supv[pb.z * 32 + lane];
            float w0 = __int_as_float(pa.y), w1 = __int_as_float(pa.w);
            float w2 = __int_as_float(pb.y), w3 = __int_as_float(pb.w);
            float2 p;
            p = bf2f(v0.x); acc.x += w0 * p.x; acc.y += w0 * p.y;
            p = bf2f(v0.y); acc.z += w0 * p.x; acc.w += w0 * p.y;
            p = bf2f(v1.x); acc.x += w1 * p.x; acc.y += w1 * p.y;
            p = bf2f(v1.y); acc.z += w1 * p.x; acc.w += w1 * p.y;
            p = bf2f(v2.x); acc.x += w2 * p.x; acc.y += w2 * p.y;
            p = bf2f(v2.y); acc.z += w2 * p.x; acc.w += w2 * p.y;
            p = bf2f(v3.x); acc.x += w3 * p.x; acc.y += w3 * p.y;
            p = bf2f(v3.y); acc.z += w3 * p.x; acc.w += w3 * p.y;
        }
        for (; i + 1 < e; i += 2) {
            int4 pa = ew4[i >> 1];
            edge(pa.x, __int_as_float(pa.y));
            edge(pa.z, __int_as_float(pa.w));
        }
        if (i < e) { int2 p = ew2[i]; edge(p.x, __int_as_float(p.y)); }

        float4 b = reinterpret_cast<const float4*>(bias)[lane];
        acc.x += b.x; acc.y += b.y; acc.z += b.z; acc.w += b.w;
        if (RELU) {
            acc.x = fmaxf(acc.x, 0.f); acc.y = fmaxf(acc.y, 0.f);
            acc.z = fmaxf(acc.z, 0.f); acc.w = fmaxf(acc.w, 0.f);
        }
        reinterpret_cast<float4*>(out)[gw * 32 + lane] = acc;
    } else {  // D == 64
        const unsigned* supv = reinterpret_cast<const unsigned*>(sup);
        float2 acc = make_float2(0.f, 0.f);
        int i = s;

        auto edge = [&](int sn, float wn) {
            float2 p = bf2f(supv[sn * 32 + lane]);
            acc.x += wn * p.x; acc.y += wn * p.y;
        };

        if (i < e && (i & 1)) { int2 p = ew2[i]; edge(p.x, __int_as_float(p.y)); i++; }
        for (; i + 3 < e; i += 4) {
            int4 pa = ew4[i >> 1];
            int4 pb = ew4[(i >> 1) + 1];
            unsigned v0 = supv[pa.x * 32 + lane];
            unsigned v1 = supv[pa.z * 32 + lane];
            unsigned v2 = supv[pb.x * 32 + lane];
            unsigned v3 = supv[pb.z * 32 + lane];
            float w0 = __int_as_float(pa.y), w1 = __int_as_float(pa.w);
            float w2 = __int_as_float(pb.y), w3 = __int_as_float(pb.w);
            float2 p;
            p = bf2f(v0); acc.x += w0 * p.x; acc.y += w0 * p.y;
            p = bf2f(v1); acc.x += w1 * p.x; acc.y += w1 * p.y;
            p = bf2f(v2); acc.x += w2 * p.x; acc.y += w2 * p.y;
            p = bf2f(v3); acc.x += w3 * p.x; acc.y += w3 * p.y;
        }
        for (; i + 1 < e; i += 2) {
            int4 pa = ew4[i >> 1];
            edge(pa.x, __int_as_float(pa.y));
            edge(pa.z, __int_as_float(pa.w));
        }
        if (i < e) { int2 p = ew2[i]; edge(p.x, __int_as_float(p.y)); }

        float2 b = reinterpret_cast<const float2*>(bias)[lane];
        acc.x += b.x; acc.y += b.y;
        if (RELU) { acc.x = fmaxf(acc.x, 0.f); acc.y = fmaxf(acc.y, 0.f); }
        reinterpret_cast<float2*>(out)[gw * 32 + lane] = acc;
    }
}

// ---------------- host-side PDL launch helper ----------------
template <typename F, typename... Args>
static void pdl_launch(F f, dim3 grid, dim3 block, size_t smem, Args... args) {
    cudaLaunchConfig_t cfg = {};
    cudaLaunchAttribute at;
    at.id = cudaLaunchAttributeProgrammaticStreamSerialization;
    at.val.programmaticStreamSerializationAllowed = 1;
    cfg.gridDim = grid;
    cfg.blockDim = block;
    cfg.dynamicSmemBytes = smem;
    cfg.stream = 0;
    cfg.attrs = &at;
    cfg.numAttrs = 1;
    cudaLaunchKernelEx(&cfg, f, args...);
}

// ---------------- launch ----------------
extern "C" void kernel_launch(void* const* d_in, const int* in_sizes, int n_in,
                              void* d_out, int out_size) {
    const float* x        = (const float*)d_in[0];
    const int*   edge_src = (const int*)  d_in[1];
    const int*   edge_dst = (const int*)  d_in[2];
    const float* edge_w   = (const float*)d_in[3];
    const float* W0 = (const float*)d_in[4];  const float* b0 = (const float*)d_in[5];
    const float* W1 = (const float*)d_in[6];  const float* b1 = (const float*)d_in[7];
    const float* W2 = (const float*)d_in[8];  const float* b2 = (const float*)d_in[9];
    const float* W3 = (const float*)d_in[10]; const float* b3 = (const float*)d_in[11];
    float* out = (float*)d_out;

    __nv_bfloat16* support; cudaGetSymbolAddress((void**)&support, g_support);
    float* h;               cudaGetSymbolAddress((void**)&h, g_h);
    int*   cursor;          cudaGetSymbolAddress((void**)&cursor, g_cursor);
    unsigned char* wih;     cudaGetSymbolAddress((void**)&wih, g_wimg_hi);
    unsigned char* wil;     cudaGetSymbolAddress((void**)&wil, g_wimg_lo);

    const int NB_SPMM = (N_NODES + 7) / 8;      // 8 warps/block
    constexpr size_t SM128 = 2 * 128 * 144 + 2 * 128 * 144;   // 73728
    constexpr size_t SM64  = 2 * 128 * 144 + 2 * 64 * 144;    // 55296

    cudaFuncSetAttribute(mma_gemm_kernel<128, true>,
                         cudaFuncAttributeMaxDynamicSharedMemorySize, SM128);
    cudaFuncSetAttribute(mma_gemm_kernel<128, false>,
                         cudaFuncAttributeMaxDynamicSharedMemorySize, SM128);
    cudaFuncSetAttribute(mma_gemm_kernel<64, false>,
                         cudaFuncAttributeMaxDynamicSharedMemorySize, SM64);

    cudaMemsetAsync(cursor, 0, N_NODES * sizeof(int), 0);

    // weight images (transpose + hi/lo split + padded rows)
    prep_weights_kernel<<<224, 256>>>(W0, W1, W2, W3);

    // layer-0 GEMM (HMMA split-bf16) fused with edge histogram
    pdl_launch(mma_gemm_kernel<128, true>, dim3(NB_GEMM_C), dim3(256), SM128,
               x, (const unsigned char*)wih, (const unsigned char*)wil,
               support, edge_dst);

    // CSR: scan + scatter
    pdl_launch(scan_blocks_kernel, dim3(NBLK_SCAN), dim3(512), (size_t)0);
    pdl_launch(scatter_kernel, dim3(NB_EDGE_C), dim3(256), (size_t)0,
               edge_src, edge_dst, edge_w);

    // layer 0 aggregate
    pdl_launch(spmm_kernel<128, true>, dim3(NB_SPMM), dim3(256), (size_t)0,
               (const __nv_bfloat16*)support, b0, h);
    // layer 1
    pdl_launch(mma_gemm_kernel<128, false>, dim3(NB_GEMM_C), dim3(256), SM128,
               (const float*)h, (const unsigned char*)(wih + 36864),
               (const unsigned char*)(wil + 36864), support, edge_dst);
    pdl_launch(spmm_kernel<128, true>, dim3(NB_SPMM), dim3(256), (size_t)0,
               (const __nv_bfloat16*)support, b1, h);
    // layer 2
    pdl_launch(mma_gemm_kernel<128, false>, dim3(NB_GEMM_C), dim3(256), SM128,
               (const float*)h, (const unsigned char*)(wih + 73728),
               (const unsigned char*)(wil + 73728), support, edge_dst);
    pdl_launch(spmm_kernel<128, true>, dim3(NB_SPMM), dim3(256), (size_t)0,
               (const __nv_bfloat16*)support, b2, h);
    // layer 3 (d=64, no relu) -> d_out
    pdl_launch(mma_gemm_kernel<64, false>, dim3(NB_GEMM_C), dim3(256), SM64,
               (const float*)h, (const unsigned char*)(wih + 110592),
               (const unsigned char*)(wil + 110592), support, edge_dst);
    pdl_launch(spmm_kernel<64, false>, dim3(NB_SPMM), dim3(256), (size_t)0,
               (const __nv_bfloat16*)support, b3, out);
}